// round 6
// baseline (speedup 1.0000x reference)
#include <cuda_runtime.h>
#include <cstdint>

#define N_NODES 50000
#define F_DIM 512
#define C_DIM 64
#define O_DIM 256
#define GRID_MAX 152
#define NT 128
#define NTILES ((N_NODES + NT - 1) / NT)   // 391

typedef unsigned long long ull;

// Scratch (static device arrays; no allocation)
__device__ float g_Mpart[GRID_MAX * C_DIM * F_DIM];   // per-block partial M = s^T x
__device__ float g_cspart[GRID_MAX * C_DIM];          // per-block partial colsum(s)
__device__ float g_M[C_DIM * F_DIM];
__device__ float g_cs[C_DIM];
__device__ float g_pooled[C_DIM * F_DIM];
__device__ unsigned g_bar;                            // monotonic grid barrier counter

static __device__ __forceinline__ ull pack2(float lo, float hi) {
    ull r; asm("mov.b64 %0, {%1,%2};" : "=l"(r) : "f"(lo), "f"(hi)); return r;
}
static __device__ __forceinline__ void unpack2(ull v, float& lo, float& hi) {
    asm("mov.b64 {%0,%1}, %2;" : "=f"(lo), "=f"(hi) : "l"(v));
}
static __device__ __forceinline__ ull fma2(ull a, ull b, ull c) {
    ull d; asm("fma.rn.f32x2 %0, %1, %2, %3;" : "=l"(d) : "l"(a), "l"(b), "l"(c)); return d;
}

// Grid-wide barrier: persistent kernel, all CTAs resident (grid == #SMs, occ 1).
// Monotonic counter -> safe across graph replays (each launch advances by 3*grid).
static __device__ __forceinline__ void grid_sync() {
    __syncthreads();
    __threadfence();
    if (threadIdx.x == 0) {
        unsigned old = atomicAdd(&g_bar, 1u);
        unsigned target = old - (old % gridDim.x) + gridDim.x;
        while (*(volatile unsigned*)&g_bar < target) __nanosleep(64);
    }
    __syncthreads();
}

// Fused: logits -> softmax -> M += s^T x (persistent tiles), then grid-sync'd
// reduction + pooled = M@We + cs(x)be + out = pooled@Wo + bo, all in one kernel.
// smem: Wp[512][64] (128KB) + x chunk [32 k4][128 n] float4 swizzled (64KB)
//       + s [128][64] (32KB) + csum[64]
__global__ __launch_bounds__(512, 1) void k1_fused(
    const float* __restrict__ x, const float* __restrict__ Wp, const float* __restrict__ bp,
    const float* __restrict__ We, const float* __restrict__ be,
    const float* __restrict__ Wo, const float* __restrict__ bo,
    float* __restrict__ out)
{
    extern __shared__ float sm[];
    float*  WpS = sm;                                 // 32768 floats
    float4* xs4 = (float4*)(sm + 32768);              // 4096 cells (16B each)
    float4* ss4 = (float4*)(sm + 32768 + 16384);      // 2048 cells
    float*  csS = sm + 32768 + 16384 + 8192;          // 64 floats

    const int tid = threadIdx.x;

    // Stage Wp once (global [512][64] row-major -> same layout in smem)
    {
        const float4* src = (const float4*)Wp;
        float4* dst = (float4*)WpS;
        #pragma unroll
        for (int it = 0; it < 16; ++it) dst[tid + it*512] = src[tid + it*512];
    }
    if (tid < 64) csS[tid] = 0.f;

    // Phase A/B ownership
    const int cq = tid & 15, nq = tid >> 4, n0 = nq * 4;
    // Phase C ownership: 8 clusters x 2 features per thread
    const int w    = tid >> 5, lane = tid & 31;
    const int co   = w >> 1;                       // cluster octet 0..7
    const int fp   = ((w & 1) << 5) | lane;        // f-pair 0..63 per kc chunk
    const int k4c  = fp >> 1, hh = fp & 1;
    const int swc  = k4c & 7;
    const float4 bp4 = ((const float4*)bp)[cq];

    ull Macc[4][8];
    #pragma unroll
    for (int a = 0; a < 4; ++a)
        #pragma unroll
        for (int b = 0; b < 8; ++b) Macc[a][b] = 0ull;
    float cs0 = 0.f, cs1 = 0.f, cs2 = 0.f, cs3 = 0.f;

    for (int tile = blockIdx.x; tile < NTILES; tile += gridDim.x) {
        const int node0 = tile * NT;

        // ---------------- Phase A: logits = x @ Wp + bp ----------------
        ull acc[4][2];
        #pragma unroll
        for (int i = 0; i < 4; ++i) {
            acc[i][0] = pack2(bp4.x, bp4.y);
            acc[i][1] = pack2(bp4.z, bp4.w);
        }

        #pragma unroll
        for (int kc = 0; kc < 4; ++kc) {
            __syncthreads();
            #pragma unroll
            for (int it = 0; it < 8; ++it) {
                int j = tid + it * 512;
                int k4 = j & 31, n = j >> 5;
                int node = node0 + n;
                float4 v = make_float4(0.f, 0.f, 0.f, 0.f);
                if (node < N_NODES) v = *(const float4*)(x + (size_t)node * F_DIM + kc * 128 + k4 * 4);
                xs4[k4 * 128 + (n ^ (k4 & 7))] = v;
            }
            __syncthreads();

            #pragma unroll 2
            for (int k4 = 0; k4 < 32; ++k4) {
                float4 xv[4];
                #pragma unroll
                for (int i = 0; i < 4; ++i) xv[i] = xs4[k4 * 128 + ((n0 + i) ^ (k4 & 7))];
                #pragma unroll
                for (int j = 0; j < 4; ++j) {
                    ulonglong2 w2 = *(const ulonglong2*)(WpS + (kc * 128 + k4 * 4 + j) * 64 + cq * 4);
                    #pragma unroll
                    for (int i = 0; i < 4; ++i) {
                        float xj = (j == 0) ? xv[i].x : (j == 1) ? xv[i].y : (j == 2) ? xv[i].z : xv[i].w;
                        ull xx = pack2(xj, xj);
                        acc[i][0] = fma2(w2.x, xx, acc[i][0]);
                        acc[i][1] = fma2(w2.y, xx, acc[i][1]);
                    }
                }
            }
        }

        // ---------------- Phase B: softmax over clusters ----------------
        #pragma unroll
        for (int i = 0; i < 4; ++i) {
            float l0, l1, l2, l3;
            unpack2(acc[i][0], l0, l1);
            unpack2(acc[i][1], l2, l3);
            float m = fmaxf(fmaxf(l0, l1), fmaxf(l2, l3));
            #pragma unroll
            for (int d = 1; d < 16; d <<= 1) m = fmaxf(m, __shfl_xor_sync(0xffffffffu, m, d));
            float e0 = __expf(l0 - m), e1 = __expf(l1 - m), e2 = __expf(l2 - m), e3 = __expf(l3 - m);
            float s = e0 + e1 + e2 + e3;
            #pragma unroll
            for (int d = 1; d < 16; d <<= 1) s += __shfl_xor_sync(0xffffffffu, s, d);
            float r = __frcp_rn(s);
            float4 sv = make_float4(e0 * r, e1 * r, e2 * r, e3 * r);
            if (node0 + n0 + i >= N_NODES) sv = make_float4(0.f, 0.f, 0.f, 0.f);
            cs0 += sv.x; cs1 += sv.y; cs2 += sv.z; cs3 += sv.w;
            ss4[(n0 + i) * 16 + cq] = sv;
        }

        // ------- Phase C: M[c][f] += s[n][c] * x[n][f]  (8c x 2f per thread) -------
        #pragma unroll
        for (int kc = 0; kc < 4; ++kc) {
            __syncthreads();
            #pragma unroll
            for (int it = 0; it < 8; ++it) {
                int j = tid + it * 512;
                int k4 = j & 31, n = j >> 5;
                int node = node0 + n;
                float4 v = make_float4(0.f, 0.f, 0.f, 0.f);
                if (node < N_NODES) v = *(const float4*)(x + (size_t)node * F_DIM + kc * 128 + k4 * 4);
                xs4[k4 * 128 + (n ^ (k4 & 7))] = v;
            }
            __syncthreads();

            const ull* xrow = (const ull*)((const char*)xs4 + k4c * 2048 + hh * 8);
            #pragma unroll 4
            for (int n = 0; n < NT; ++n) {
                float4 s0 = ss4[n * 16 + co * 2];       // broadcast (warp-uniform)
                float4 s1 = ss4[n * 16 + co * 2 + 1];   // broadcast
                ull xv = xrow[(n ^ swc) * 2];           // LDS.64, 2-way floor, no extra conflicts
                Macc[kc][0] = fma2(xv, pack2(s0.x, s0.x), Macc[kc][0]);
                Macc[kc][1] = fma2(xv, pack2(s0.y, s0.y), Macc[kc][1]);
                Macc[kc][2] = fma2(xv, pack2(s0.z, s0.z), Macc[kc][2]);
                Macc[kc][3] = fma2(xv, pack2(s0.w, s0.w), Macc[kc][3]);
                Macc[kc][4] = fma2(xv, pack2(s1.x, s1.x), Macc[kc][4]);
                Macc[kc][5] = fma2(xv, pack2(s1.y, s1.y), Macc[kc][5]);
                Macc[kc][6] = fma2(xv, pack2(s1.z, s1.z), Macc[kc][6]);
                Macc[kc][7] = fma2(xv, pack2(s1.w, s1.w), Macc[kc][7]);
            }
        }
    }

    // Write per-block partial M (float2 per (kc,cc), coalesced across lanes)
    #pragma unroll
    for (int kc = 0; kc < 4; ++kc)
        #pragma unroll
        for (int cc = 0; cc < 8; ++cc) {
            float a, b;
            unpack2(Macc[kc][cc], a, b);
            int c = co * 8 + cc;
            int f = kc * 128 + fp * 2;
            *(float2*)(g_Mpart + (size_t)blockIdx.x * (C_DIM * F_DIM) + c * F_DIM + f) =
                make_float2(a, b);
        }

    // Per-block partial colsum(s)
    atomicAdd(&csS[cq * 4 + 0], cs0);
    atomicAdd(&csS[cq * 4 + 1], cs1);
    atomicAdd(&csS[cq * 4 + 2], cs2);
    atomicAdd(&csS[cq * 4 + 3], cs3);
    __syncthreads();
    if (tid < 64) g_cspart[blockIdx.x * 64 + tid] = csS[tid];

    // ================= In-kernel epilogue (grid-synchronized) =================
    const int G = gridDim.x;
    const unsigned g = blockIdx.x * 512u + (unsigned)tid;

    grid_sync();

    // Reduce partials: M (32768 outputs, coalesced) + cs (64)
    if (g < C_DIM * F_DIM) {
        float s = 0.f;
        #pragma unroll 4
        for (int b = 0; b < G; ++b) s += g_Mpart[(size_t)b * (C_DIM * F_DIM) + g];
        g_M[g] = s;
    } else if (g < C_DIM * F_DIM + C_DIM) {
        int c = (int)g - C_DIM * F_DIM;
        float s = 0.f;
        #pragma unroll 4
        for (int b = 0; b < G; ++b) s += g_cspart[b * C_DIM + c];
        g_cs[c] = s;
    }

    grid_sync();

    // pooled = M @ We + cs (x) be : blocks 0..15, 4 clusters per block, f = tid
    if (blockIdx.x < 16) {
        const int f = tid;
        const int c0 = blockIdx.x * 4;
        const float bef = be[f];
        float a0 = g_cs[c0 + 0] * bef;
        float a1 = g_cs[c0 + 1] * bef;
        float a2 = g_cs[c0 + 2] * bef;
        float a3 = g_cs[c0 + 3] * bef;
        #pragma unroll 8
        for (int k = 0; k < F_DIM; ++k) {
            float wv = We[(size_t)k * F_DIM + f];      // coalesced
            a0 += g_M[(c0 + 0) * F_DIM + k] * wv;      // broadcast
            a1 += g_M[(c0 + 1) * F_DIM + k] * wv;
            a2 += g_M[(c0 + 2) * F_DIM + k] * wv;
            a3 += g_M[(c0 + 3) * F_DIM + k] * wv;
        }
        g_pooled[(c0 + 0) * F_DIM + f] = a0;
        g_pooled[(c0 + 1) * F_DIM + f] = a1;
        g_pooled[(c0 + 2) * F_DIM + f] = a2;
        g_pooled[(c0 + 3) * F_DIM + f] = a3;
    }

    grid_sync();

    // out = pooled @ Wo + bo : blocks 0..31, 2 clusters per block
    if (blockIdx.x < 32) {
        const int o = tid & 255;
        const int c = blockIdx.x * 2 + (tid >> 8);
        float acc = bo[o];
        #pragma unroll 8
        for (int f = 0; f < F_DIM; ++f)
            acc += g_pooled[c * F_DIM + f] * Wo[(size_t)f * O_DIM + o];
        out[c * O_DIM + o] = acc;
    }
}

extern "C" void kernel_launch(void* const* d_in, const int* in_sizes, int n_in,
                              void* d_out, int out_size) {
    const float* x  = (const float*)d_in[0];
    // d_in[1] = edge_index (int64), d_in[2] = batch (int64): unused by the output
    const float* Wp = (const float*)d_in[3];
    const float* bp = (const float*)d_in[4];
    const float* We = (const float*)d_in[5];
    const float* be = (const float*)d_in[6];
    const float* Wo = (const float*)d_in[7];
    const float* bo = (const float*)d_in[8];
    float* out = (float*)d_out;

    // Grid = #SMs so every CTA is resident (occ=1 at this smem size) -> the
    // software grid barrier cannot deadlock. Queried host-side (runs at
    // capture time only; grid dims are baked into the graph).
    int dev = 0;
    cudaGetDevice(&dev);
    int smc = GRID_MAX;
    cudaDeviceGetAttribute(&smc, cudaDevAttrMultiProcessorCount, dev);
    int G = smc < GRID_MAX ? smc : GRID_MAX;

    const int SMEM1 = (32768 + 16384 + 8192 + 64) * (int)sizeof(float);  // 229632 B
    cudaFuncSetAttribute(k1_fused, cudaFuncAttributeMaxDynamicSharedMemorySize, SMEM1);

    k1_fused<<<G, 512, SMEM1>>>(x, Wp, bp, We, be, Wo, bo, out);
}